// round 1
// baseline (speedup 1.0000x reference)
#include <cuda_runtime.h>

// ---------------------------------------------------------------------------
// MixResidualBlockC: per-sample mixture-of-kernels 1x1 conv chain.
//   mix[b,m]   = lat @ w_dyna^T + b_dyna
//   W_*[b]     = sum_m mix[b,m] * bank_*[m]      (stored TRANSPOSED [K][M])
//   short      = k_short @ x + b_short
//   h1c        = [sin; cos](k_in @ x + b_in)
//   h2c        = [sin; cos](k_mid @ h1c + b_mid)
//   out        = k_out @ h2c + b_out + short
// B=16, FIN=FOUT=FH2=256, NMIX=8, LAT=512, HW=4096
// ---------------------------------------------------------------------------

#define BM 128
#define BN 128
#define BK 16

// -------------------- device scratch (no allocs allowed) -------------------
__device__ float g_mix[16 * 8];
__device__ float g_w1t[16 * 256 * 512];    // [b][k=in(256)][m=out(512: k_in rows 0-255, k_short 256-511)]
__device__ float g_wmidt[16 * 512 * 256];  // [b][k=in(512)][m=out(256)]
__device__ float g_woutt[16 * 512 * 256];
__device__ float g_b1[16 * 512];           // b_in(0-255) ; b_short(256-511)
__device__ float g_bmid[16 * 256];
__device__ float g_bout[16 * 256];
__device__ float g_h1[(size_t)16 * 512 * 4096];  // sincos(stage1)
__device__ float g_h2[(size_t)16 * 512 * 4096];  // sincos(stage2)

// -------------------- packed f32x2 helpers (Blackwell) ---------------------
__device__ __forceinline__ unsigned long long pack2(float x, float y) {
    unsigned long long r;
    asm("mov.b64 %0, {%1, %2};" : "=l"(r) : "f"(x), "f"(y));
    return r;
}
__device__ __forceinline__ void unpack2(unsigned long long v, float& x, float& y) {
    asm("mov.b64 {%0, %1}, %2;" : "=f"(x), "=f"(y) : "l"(v));
}
__device__ __forceinline__ void fma2(unsigned long long& d, unsigned long long a,
                                     unsigned long long b) {
    asm("fma.rn.f32x2 %0, %1, %2, %0;" : "+l"(d) : "l"(a), "l"(b));
}

// -------------------- K0: mixing coefficients -------------------------------
__global__ void mix_kernel(const float* __restrict__ lat, const float* __restrict__ wd,
                           const float* __restrict__ bd) {
    int t = threadIdx.x;
    if (t < 128) {
        int b = t >> 3, m = t & 7;
        float a = bd[m];
        const float* lp = lat + b * 512;
        const float* wp = wd + m * 512;
        #pragma unroll 8
        for (int l = 0; l < 512; l++) a += lp[l] * wp[l];
        g_mix[t] = a;  // [b][m]
    }
}

// -------------------- K1: mix weight banks into per-sample (transposed) ----
__global__ void prep_kernel(const float* __restrict__ kin, const float* __restrict__ kmid,
                            const float* __restrict__ kout, const float* __restrict__ kshort,
                            const float* __restrict__ bin, const float* __restrict__ bmid,
                            const float* __restrict__ bout, const float* __restrict__ bshort) {
    __shared__ float smix[128];
    if (threadIdx.x < 128) smix[threadIdx.x] = g_mix[threadIdx.x];
    __syncthreads();

    int p = blockIdx.x * 256 + threadIdx.x;
    float v[8];

    if (p < 65536) {  // k_in [8][256][256] -> g_w1t rows 0-255
        int r = p >> 8, c = p & 255;
        #pragma unroll
        for (int m = 0; m < 8; m++) v[m] = kin[m * 65536 + p];
        int di = c * 512 + r;
        #pragma unroll
        for (int b = 0; b < 16; b++) {
            float a = 0.f;
            #pragma unroll
            for (int m = 0; m < 8; m++) a += smix[b * 8 + m] * v[m];
            g_w1t[b * 131072 + di] = a;
        }
    } else if (p < 131072) {  // k_short -> g_w1t rows 256-511
        int q = p - 65536;
        int r = q >> 8, c = q & 255;
        #pragma unroll
        for (int m = 0; m < 8; m++) v[m] = kshort[m * 65536 + q];
        int di = c * 512 + 256 + r;
        #pragma unroll
        for (int b = 0; b < 16; b++) {
            float a = 0.f;
            #pragma unroll
            for (int m = 0; m < 8; m++) a += smix[b * 8 + m] * v[m];
            g_w1t[b * 131072 + di] = a;
        }
    } else if (p < 262144) {  // k_mid [8][256][512]
        int q = p - 131072;
        int r = q >> 9, c = q & 511;
        #pragma unroll
        for (int m = 0; m < 8; m++) v[m] = kmid[m * 131072 + q];
        int di = c * 256 + r;
        #pragma unroll
        for (int b = 0; b < 16; b++) {
            float a = 0.f;
            #pragma unroll
            for (int m = 0; m < 8; m++) a += smix[b * 8 + m] * v[m];
            g_wmidt[b * 131072 + di] = a;
        }
    } else if (p < 393216) {  // k_out [8][256][512]
        int q = p - 262144;
        int r = q >> 9, c = q & 511;
        #pragma unroll
        for (int m = 0; m < 8; m++) v[m] = kout[m * 131072 + q];
        int di = c * 256 + r;
        #pragma unroll
        for (int b = 0; b < 16; b++) {
            float a = 0.f;
            #pragma unroll
            for (int m = 0; m < 8; m++) a += smix[b * 8 + m] * v[m];
            g_woutt[b * 131072 + di] = a;
        }
    } else if (p < 394240) {  // biases: 4 x [8][256]
        int q = p - 393216;
        int which = q >> 8, r = q & 255;
        const float* s = (which == 0) ? bin : (which == 1) ? bshort : (which == 2) ? bmid : bout;
        #pragma unroll
        for (int m = 0; m < 8; m++) v[m] = s[m * 256 + r];
        #pragma unroll
        for (int b = 0; b < 16; b++) {
            float a = 0.f;
            #pragma unroll
            for (int m = 0; m < 8; m++) a += smix[b * 8 + m] * v[m];
            if (which == 0)      g_b1[b * 512 + r] = a;
            else if (which == 1) g_b1[b * 512 + 256 + r] = a;
            else if (which == 2) g_bmid[b * 256 + r] = a;
            else                 g_bout[b * 256 + r] = a;
        }
    }
}

// -------------------- fused SGEMM (f32x2), MODE-specific epilogue ----------
// MODE 0: M=512,K=256, W=g_w1t, X=x.  rows<256 -> sincos->g_h1 ; rows>=256 -> out (short path)
// MODE 1: M=256,K=512, W=g_wmidt, X=g_h1.  sincos -> g_h2
// MODE 2: M=256,K=512, W=g_woutt, X=g_h2.  out += v
template <int MODE>
__global__ void __launch_bounds__(256, 2)
gemm_fused(const float* __restrict__ xin, float* __restrict__ out) {
    constexpr int M = (MODE == 0) ? 512 : 256;
    constexpr int K = (MODE == 0) ? 256 : 512;
    constexpr int NK = K / BK;

    const int b = blockIdx.z;
    const int mt = blockIdx.y;
    const int nt = blockIdx.x;

    const float* __restrict__ W;
    const float* __restrict__ X;
    const float* __restrict__ bias;
    if constexpr (MODE == 0) {
        W = g_w1t + (size_t)b * (K * M);
        X = xin + (size_t)b * (256 * 4096);
        bias = g_b1 + b * 512;
    } else if constexpr (MODE == 1) {
        W = g_wmidt + (size_t)b * (K * M);
        X = g_h1 + (size_t)b * ((size_t)512 * 4096);
        bias = g_bmid + b * 256;
    } else {
        W = g_woutt + (size_t)b * (K * M);
        X = g_h2 + (size_t)b * ((size_t)512 * 4096);
        bias = g_bout + b * 256;
    }

    __shared__ float As[2][BK][BM];  // [k][m], W is stored transposed [K][M]
    __shared__ float Bs[2][BK][BN];

    const int tid = threadIdx.x;
    const int lk = tid >> 5;          // 0..7
    const int lc = (tid & 31) << 2;   // 0..124 step 4

    const float* Ag = W + (size_t)lk * M + mt * BM + lc;
    const float* Bg = X + (size_t)lk * 4096 + nt * BN + lc;

    float4 ra0 = *(const float4*)(Ag);
    float4 ra1 = *(const float4*)(Ag + 8 * M);
    float4 rb0 = *(const float4*)(Bg);
    float4 rb1 = *(const float4*)(Bg + 8 * 4096);

    *(float4*)&As[0][lk][lc] = ra0;
    *(float4*)&As[0][lk + 8][lc] = ra1;
    *(float4*)&Bs[0][lk][lc] = rb0;
    *(float4*)&Bs[0][lk + 8][lc] = rb1;
    __syncthreads();

    unsigned long long acc[8][4];
    #pragma unroll
    for (int i = 0; i < 8; i++)
        #pragma unroll
        for (int j = 0; j < 4; j++) acc[i][j] = 0ULL;

    const int tr8 = (tid >> 4) << 3;
    const int tc8 = (tid & 15) << 3;

    int buf = 0;
    for (int kt = 0; kt < NK; kt++) {
        if (kt + 1 < NK) {
            const float* An = Ag + (size_t)(kt + 1) * BK * M;
            const float* Bn = Bg + (size_t)(kt + 1) * BK * 4096;
            ra0 = *(const float4*)(An);
            ra1 = *(const float4*)(An + 8 * M);
            rb0 = *(const float4*)(Bn);
            rb1 = *(const float4*)(Bn + 8 * 4096);
        }
        #pragma unroll
        for (int kk = 0; kk < BK; kk++) {
            float4 a0 = *(const float4*)&As[buf][kk][tr8];
            float4 a1 = *(const float4*)&As[buf][kk][tr8 + 4];
            float4 b0 = *(const float4*)&Bs[buf][kk][tc8];
            float4 b1 = *(const float4*)&Bs[buf][kk][tc8 + 4];
            unsigned long long bb0 = pack2(b0.x, b0.y);
            unsigned long long bb1 = pack2(b0.z, b0.w);
            unsigned long long bb2 = pack2(b1.x, b1.y);
            unsigned long long bb3 = pack2(b1.z, b1.w);
            float av[8] = {a0.x, a0.y, a0.z, a0.w, a1.x, a1.y, a1.z, a1.w};
            #pragma unroll
            for (int i = 0; i < 8; i++) {
                unsigned long long aa = pack2(av[i], av[i]);
                fma2(acc[i][0], aa, bb0);
                fma2(acc[i][1], aa, bb1);
                fma2(acc[i][2], aa, bb2);
                fma2(acc[i][3], aa, bb3);
            }
        }
        if (kt + 1 < NK) {
            __syncthreads();
            buf ^= 1;
            *(float4*)&As[buf][lk][lc] = ra0;
            *(float4*)&As[buf][lk + 8][lc] = ra1;
            *(float4*)&Bs[buf][lk][lc] = rb0;
            *(float4*)&Bs[buf][lk + 8][lc] = rb1;
            __syncthreads();
        }
    }

    // ---------------- epilogue ----------------
    const int gr0 = mt * BM + tr8;
    const size_t n0 = (size_t)nt * BN + tc8;

    #pragma unroll
    for (int i = 0; i < 8; i++) {
        const int gr = gr0 + i;
        const float bv = bias[gr];
        float v[8];
        unpack2(acc[i][0], v[0], v[1]);
        unpack2(acc[i][1], v[2], v[3]);
        unpack2(acc[i][2], v[4], v[5]);
        unpack2(acc[i][3], v[6], v[7]);
        #pragma unroll
        for (int t = 0; t < 8; t++) v[t] += bv;

        if constexpr (MODE == 0) {
            if (mt < 2) {  // k_in rows -> sincos into g_h1
                float s[8], c[8];
                #pragma unroll
                for (int t = 0; t < 8; t++) __sincosf(v[t], &s[t], &c[t]);
                float* hs = g_h1 + ((size_t)b * 512 + gr) * 4096 + n0;
                float* hc = hs + (size_t)256 * 4096;
                *(float4*)(hs) = make_float4(s[0], s[1], s[2], s[3]);
                *(float4*)(hs + 4) = make_float4(s[4], s[5], s[6], s[7]);
                *(float4*)(hc) = make_float4(c[0], c[1], c[2], c[3]);
                *(float4*)(hc + 4) = make_float4(c[4], c[5], c[6], c[7]);
            } else {  // k_short rows -> out (initialize)
                float* o = out + ((size_t)b * 256 + (gr - 256)) * 4096 + n0;
                *(float4*)(o) = make_float4(v[0], v[1], v[2], v[3]);
                *(float4*)(o + 4) = make_float4(v[4], v[5], v[6], v[7]);
            }
        } else if constexpr (MODE == 1) {
            float s[8], c[8];
            #pragma unroll
            for (int t = 0; t < 8; t++) __sincosf(v[t], &s[t], &c[t]);
            float* hs = g_h2 + ((size_t)b * 512 + gr) * 4096 + n0;
            float* hc = hs + (size_t)256 * 4096;
            *(float4*)(hs) = make_float4(s[0], s[1], s[2], s[3]);
            *(float4*)(hs + 4) = make_float4(s[4], s[5], s[6], s[7]);
            *(float4*)(hc) = make_float4(c[0], c[1], c[2], c[3]);
            *(float4*)(hc + 4) = make_float4(c[4], c[5], c[6], c[7]);
        } else {  // MODE 2: accumulate onto short path
            float* o = out + ((size_t)b * 256 + gr) * 4096 + n0;
            float4 o0 = *(const float4*)(o);
            float4 o1 = *(const float4*)(o + 4);
            o0.x += v[0]; o0.y += v[1]; o0.z += v[2]; o0.w += v[3];
            o1.x += v[4]; o1.y += v[5]; o1.z += v[6]; o1.w += v[7];
            *(float4*)(o) = o0;
            *(float4*)(o + 4) = o1;
        }
    }
}

// -------------------- launch -------------------------------------------------
extern "C" void kernel_launch(void* const* d_in, const int* in_sizes, int n_in,
                              void* d_out, int out_size) {
    const float* x        = (const float*)d_in[0];
    const float* lat      = (const float*)d_in[1];
    const float* k_in_mix = (const float*)d_in[2];
    const float* k_mid_mix  = (const float*)d_in[3];
    const float* k_out_mix  = (const float*)d_in[4];
    const float* k_short_mix= (const float*)d_in[5];
    const float* b_in_mix   = (const float*)d_in[6];
    const float* b_mid_mix  = (const float*)d_in[7];
    const float* b_out_mix  = (const float*)d_in[8];
    const float* b_short_mix= (const float*)d_in[9];
    const float* w_dyna     = (const float*)d_in[10];
    const float* b_dyna     = (const float*)d_in[11];
    float* out = (float*)d_out;

    mix_kernel<<<1, 128>>>(lat, w_dyna, b_dyna);
    prep_kernel<<<1540, 256>>>(k_in_mix, k_mid_mix, k_out_mix, k_short_mix,
                               b_in_mix, b_mid_mix, b_out_mix, b_short_mix);
    gemm_fused<0><<<dim3(32, 4, 16), 256>>>(x, out);        // k_in + k_short
    gemm_fused<1><<<dim3(32, 2, 16), 256>>>(nullptr, out);  // k_mid
    gemm_fused<2><<<dim3(32, 2, 16), 256>>>(nullptr, out);  // k_out + residual
}

// round 3
// speedup vs baseline: 1.7190x; 1.7190x over previous
#include <cuda_runtime.h>
#include <cuda_bf16.h>
#include <cstdint>

// ============================================================================
// MixResidualBlockC via warp-level bf16 mma.sync (3-split fp32 emulation).
//   stage1: h1 = sincos(W1[256,256] @ xt)           (pixel-major bf16 hi/lo)
//   stage2: h2 = sincos(W2[256,512] @ h1)
//   stage3: out = W3[256,768] @ [h2 ; xt] + b3      (W3 = [k_out | k_short])
// CTA tile: 128 px x 128 ch.  Warp tile 64x32.  BK=64, smem rows padded 144B.
// ============================================================================

#define NPIX 4096
#define NB 16
#define STRIDE 144                     // bytes per 64-bf16 smem row (padded)
#define PLANE (128 * STRIDE)           // 18432 B per plane tile
#define BUFSZ (4 * PLANE)              // Ah|Al|Bh|Bl = 73728 B
#define SMEM_DYN (2 * BUFSZ)           // 147456 B

// -------------------- device scratch --------------------------------------
__device__ float g_mix[NB * 8];
__device__ float g_b1[NB * 256], g_b2[NB * 256], g_b3[NB * 256];
__device__ __nv_bfloat16 g_w1h[NB * 256 * 256], g_w1l[NB * 256 * 256];
__device__ __nv_bfloat16 g_w2h[NB * 256 * 512], g_w2l[NB * 256 * 512];
__device__ __nv_bfloat16 g_w3h[NB * 256 * 768], g_w3l[NB * 256 * 768];
__device__ __nv_bfloat16 g_xth[(size_t)NB * NPIX * 256], g_xtl[(size_t)NB * NPIX * 256];
__device__ __nv_bfloat16 g_h1h[(size_t)NB * NPIX * 512], g_h1l[(size_t)NB * NPIX * 512];
__device__ __nv_bfloat16 g_h2h[(size_t)NB * NPIX * 512], g_h2l[(size_t)NB * NPIX * 512];

// -------------------- PTX helpers (all arch-portable) ----------------------
__device__ __forceinline__ uint32_t smem_u32(const void* p) {
    uint32_t a;
    asm("{ .reg .u64 t; cvta.to.shared.u64 t, %1; cvt.u32.u64 %0, t; }" : "=r"(a) : "l"(p));
    return a;
}
__device__ __forceinline__ void cpa16(uint32_t dst, const void* src) {
    asm volatile("cp.async.cg.shared.global [%0], [%1], 16;" :: "r"(dst), "l"(src));
}
__device__ __forceinline__ void cpa_commit() { asm volatile("cp.async.commit_group;"); }

__device__ __forceinline__ void ldsm_x4(uint32_t* r, uint32_t addr) {
    asm volatile("ldmatrix.sync.aligned.m8n8.x4.shared.b16 {%0,%1,%2,%3}, [%4];"
                 : "=r"(r[0]), "=r"(r[1]), "=r"(r[2]), "=r"(r[3]) : "r"(addr));
}
__device__ __forceinline__ void ldsm_x2(uint32_t* r, uint32_t addr) {
    asm volatile("ldmatrix.sync.aligned.m8n8.x2.shared.b16 {%0,%1}, [%2];"
                 : "=r"(r[0]), "=r"(r[1]) : "r"(addr));
}
__device__ __forceinline__ void mma_bf16(float* d, const uint32_t* a, const uint32_t* b) {
    asm volatile(
        "mma.sync.aligned.m16n8k16.row.col.f32.bf16.bf16.f32 "
        "{%0,%1,%2,%3}, {%4,%5,%6,%7}, {%8,%9}, {%0,%1,%2,%3};"
        : "+f"(d[0]), "+f"(d[1]), "+f"(d[2]), "+f"(d[3])
        : "r"(a[0]), "r"(a[1]), "r"(a[2]), "r"(a[3]), "r"(b[0]), "r"(b[1]));
}
__device__ __forceinline__ uint32_t packbf2(float a, float b) {
    __nv_bfloat16 h0 = __float2bfloat16(a), h1 = __float2bfloat16(b);
    return (uint32_t)__bfloat16_as_ushort(h0) | ((uint32_t)__bfloat16_as_ushort(h1) << 16);
}

// -------------------- K0: mixing coefficients ------------------------------
__global__ void mix_kernel(const float* __restrict__ lat, const float* __restrict__ wd,
                           const float* __restrict__ bd) {
    int t = threadIdx.x;
    if (t < 128) {
        int b = t >> 3, m = t & 7;
        float a = bd[m];
        const float* lp = lat + b * 512;
        const float* wp = wd + m * 512;
        #pragma unroll 8
        for (int l = 0; l < 512; l++) a += lp[l] * wp[l];
        g_mix[t] = a;
    }
}

// -------------------- K1: weight mixing + bf16 hi/lo split -----------------
__global__ void prep_kernel(const float* __restrict__ kin, const float* __restrict__ kmid,
                            const float* __restrict__ kout, const float* __restrict__ ksh,
                            const float* __restrict__ bin, const float* __restrict__ bmid,
                            const float* __restrict__ bout, const float* __restrict__ bsh) {
    __shared__ float smix[128];
    if (threadIdx.x < 128) smix[threadIdx.x] = g_mix[threadIdx.x];
    __syncthreads();
    int p = blockIdx.x * 256 + threadIdx.x;
    float v[8];

    if (p < 65536) {  // w1 (k_in)
        #pragma unroll
        for (int m = 0; m < 8; m++) v[m] = kin[m * 65536 + p];
        #pragma unroll
        for (int b = 0; b < NB; b++) {
            float a = 0.f;
            #pragma unroll
            for (int m = 0; m < 8; m++) a += smix[b * 8 + m] * v[m];
            __nv_bfloat16 h = __float2bfloat16(a);
            g_w1h[b * 65536 + p] = h;
            g_w1l[b * 65536 + p] = __float2bfloat16(a - __bfloat162float(h));
        }
    } else if (p < 196608) {  // w2 (k_mid)
        int q = p - 65536;
        #pragma unroll
        for (int m = 0; m < 8; m++) v[m] = kmid[m * 131072 + q];
        #pragma unroll
        for (int b = 0; b < NB; b++) {
            float a = 0.f;
            #pragma unroll
            for (int m = 0; m < 8; m++) a += smix[b * 8 + m] * v[m];
            __nv_bfloat16 h = __float2bfloat16(a);
            g_w2h[b * 131072 + q] = h;
            g_w2l[b * 131072 + q] = __float2bfloat16(a - __bfloat162float(h));
        }
    } else if (p < 327680) {  // w3 k_out part: cols [0,512)
        int q = p - 196608;
        int o = q >> 9, i = q & 511;
        #pragma unroll
        for (int m = 0; m < 8; m++) v[m] = kout[m * 131072 + q];
        int di = o * 768 + i;
        #pragma unroll
        for (int b = 0; b < NB; b++) {
            float a = 0.f;
            #pragma unroll
            for (int m = 0; m < 8; m++) a += smix[b * 8 + m] * v[m];
            __nv_bfloat16 h = __float2bfloat16(a);
            g_w3h[b * 196608 + di] = h;
            g_w3l[b * 196608 + di] = __float2bfloat16(a - __bfloat162float(h));
        }
    } else if (p < 393216) {  // w3 k_short part: cols [512,768)
        int q = p - 327680;
        int o = q >> 8, i = q & 255;
        #pragma unroll
        for (int m = 0; m < 8; m++) v[m] = ksh[m * 65536 + q];
        int di = o * 768 + 512 + i;
        #pragma unroll
        for (int b = 0; b < NB; b++) {
            float a = 0.f;
            #pragma unroll
            for (int m = 0; m < 8; m++) a += smix[b * 8 + m] * v[m];
            __nv_bfloat16 h = __float2bfloat16(a);
            g_w3h[b * 196608 + di] = h;
            g_w3l[b * 196608 + di] = __float2bfloat16(a - __bfloat162float(h));
        }
    } else if (p < 393472) {  // biases
        int r = p - 393216;
        float vi[8], vm[8], vo[8];
        #pragma unroll
        for (int m = 0; m < 8; m++) {
            vi[m] = bin[m * 256 + r];
            vm[m] = bmid[m * 256 + r];
            vo[m] = bout[m * 256 + r] + bsh[m * 256 + r];
        }
        #pragma unroll
        for (int b = 0; b < NB; b++) {
            float a1 = 0.f, a2 = 0.f, a3 = 0.f;
            #pragma unroll
            for (int m = 0; m < 8; m++) {
                float mx = smix[b * 8 + m];
                a1 += mx * vi[m]; a2 += mx * vm[m]; a3 += mx * vo[m];
            }
            g_b1[b * 256 + r] = a1;
            g_b2[b * 256 + r] = a2;
            g_b3[b * 256 + r] = a3;
        }
    }
}

// -------------------- K2: x transpose + split  x[b,c,p] -> xt[b,p,c] -------
__global__ void xt_kernel(const float* __restrict__ x) {
    __shared__ float ts[32][33];
    int b = blockIdx.z, p0 = blockIdx.x * 32, c0 = blockIdx.y * 32;
    const float* src = x + ((size_t)b * 256 + c0) * NPIX + p0;
    for (int r = threadIdx.y; r < 32; r += 8)
        ts[r][threadIdx.x] = src[(size_t)r * NPIX + threadIdx.x];
    __syncthreads();
    int lane = threadIdx.x;
    for (int pr = threadIdx.y; pr < 32; pr += 8) {
        float v = ts[lane][pr];
        __nv_bfloat16 h = __float2bfloat16(v);
        __nv_bfloat16 l = __float2bfloat16(v - __bfloat162float(h));
        size_t di = ((size_t)b * NPIX + p0 + pr) * 256 + c0 + lane;
        g_xth[di] = h;
        g_xtl[di] = l;
    }
}

// -------------------- GEMM stage (mma.sync bf16 3-split) -------------------
template <int MODE>  // 1,2,3
__global__ void __launch_bounds__(256, 1)
gemm_stage(float* __restrict__ out) {
    constexpr int K = (MODE == 1) ? 256 : (MODE == 2) ? 512 : 768;
    constexpr int NCH = K / 64;
    constexpr int AROW = (MODE == 1) ? 256 : 512;

    extern __shared__ __align__(16) char dsm[];
    const uint32_t sbase = smem_u32(dsm);
    __shared__ float sbias[128];

    const int tid = threadIdx.x;
    const int lane = tid & 31;
    const int wid = tid >> 5;
    const int warp_m = wid & 1;       // 0..1  (64 px each)
    const int warp_n = wid >> 1;      // 0..3  (32 ch each)
    const int b = blockIdx.z;
    const int p0 = blockIdx.x * 128;
    const int cg0 = blockIdx.y * 128;

    const __nv_bfloat16 *Ah, *Al, *Bh, *Bl;
    const float* bias;
    if constexpr (MODE == 1) {
        Ah = g_xth + (size_t)b * NPIX * 256; Al = g_xtl + (size_t)b * NPIX * 256;
        Bh = g_w1h + (size_t)b * 65536;      Bl = g_w1l + (size_t)b * 65536;
        bias = g_b1 + b * 256;
    } else if constexpr (MODE == 2) {
        Ah = g_h1h + (size_t)b * NPIX * 512; Al = g_h1l + (size_t)b * NPIX * 512;
        Bh = g_w2h + (size_t)b * 131072;     Bl = g_w2l + (size_t)b * 131072;
        bias = g_b2 + b * 256;
    } else {
        Ah = g_h2h + (size_t)b * NPIX * 512; Al = g_h2l + (size_t)b * NPIX * 512;
        Bh = g_w3h + (size_t)b * 196608;     Bl = g_w3l + (size_t)b * 196608;
        bias = g_b3 + b * 256;
    }
    const __nv_bfloat16* Xh = g_xth + (size_t)b * NPIX * 256;  // MODE3 tail
    const __nv_bfloat16* Xl = g_xtl + (size_t)b * NPIX * 256;

    if (tid < 128) sbias[tid] = bias[cg0 + tid];

    // ---- chunk copier: 4096 x 16B per chunk (Ah|Al|Bh|Bl, 128 rows x 8) ----
    auto copy_chunk = [&](int ch, int buf) {
        const int k0 = ch * 64;
        const uint32_t bb = sbase + buf * BUFSZ;
        const __nv_bfloat16 *pAh = Ah, *pAl = Al;
        int acol = k0, arow = AROW;
        if (MODE == 3 && k0 >= 512) { pAh = Xh; pAl = Xl; acol = k0 - 512; arow = 256; }
        #pragma unroll
        for (int j = 0; j < 16; j++) {
            int u = tid + j * 256;
            int plane = u >> 10;          // 0 Ah, 1 Al, 2 Bh, 3 Bl
            int r = (u >> 3) & 127;
            int c = u & 7;
            uint32_t dst = bb + plane * PLANE + r * STRIDE + c * 16;
            const __nv_bfloat16* src;
            if (plane == 0)      src = pAh + (size_t)(p0 + r) * arow + acol + c * 8;
            else if (plane == 1) src = pAl + (size_t)(p0 + r) * arow + acol + c * 8;
            else if (plane == 2) src = Bh + (size_t)(cg0 + r) * K + k0 + c * 8;
            else                 src = Bl + (size_t)(cg0 + r) * K + k0 + c * 8;
            cpa16(dst, src);
        }
        cpa_commit();
    };

    // ---- ldmatrix lane address offsets ----
    const int a_row_off = (warp_m * 64 + (lane & 15)) * STRIDE + ((lane >> 4) & 1) * 16;
    const int lb = lane & 15;
    const int b_row_off = (warp_n * 32 + (lb & 7)) * STRIDE + ((lb >> 3) & 1) * 16;

    float acc[4][4][4];
    #pragma unroll
    for (int i = 0; i < 4; i++)
        #pragma unroll
        for (int j = 0; j < 4; j++)
            #pragma unroll
            for (int q = 0; q < 4; q++) acc[i][j][q] = 0.f;

    copy_chunk(0, 0);
    asm volatile("cp.async.wait_group 0;" ::: "memory");
    __syncthreads();

    for (int it = 0; it < NCH; it++) {
        const int buf = it & 1;
        if (it + 1 < NCH) copy_chunk(it + 1, buf ^ 1);
        const uint32_t bb = sbase + buf * BUFSZ;

        #pragma unroll
        for (int ks = 0; ks < 4; ks++) {
            uint32_t fAh[4][4], fAl[4][4], fBh[4][2], fBl[4][2];
            #pragma unroll
            for (int mi = 0; mi < 4; mi++) {
                uint32_t a = bb + a_row_off + mi * (16 * STRIDE) + ks * 32;
                ldsm_x4(fAh[mi], a);
                ldsm_x4(fAl[mi], a + PLANE);
            }
            #pragma unroll
            for (int ni = 0; ni < 4; ni++) {
                uint32_t a = bb + 2 * PLANE + b_row_off + ni * (8 * STRIDE) + ks * 32;
                ldsm_x2(fBh[ni], a);
                ldsm_x2(fBl[ni], a + PLANE);
            }
            #pragma unroll
            for (int mi = 0; mi < 4; mi++)
                #pragma unroll
                for (int ni = 0; ni < 4; ni++) {
                    mma_bf16(acc[mi][ni], fAh[mi], fBh[ni]);
                    mma_bf16(acc[mi][ni], fAh[mi], fBl[ni]);
                    mma_bf16(acc[mi][ni], fAl[mi], fBh[ni]);
                }
        }
        if (it + 1 < NCH) {
            asm volatile("cp.async.wait_group 0;" ::: "memory");
            __syncthreads();
        }
    }

    // ---- epilogue -----------------------------------------------------------
    const int lg = lane >> 2;          // row-in-group 0..7
    const int l2 = (lane & 3) * 2;     // col pair

    if constexpr (MODE != 3) {
        __nv_bfloat16* Hh = (MODE == 1) ? g_h1h : g_h2h;
        __nv_bfloat16* Hl = (MODE == 1) ? g_h1l : g_h2l;
        #pragma unroll
        for (int mi = 0; mi < 4; mi++) {
            const int pix = p0 + warp_m * 64 + mi * 16 + lg;
            const size_t r0 = ((size_t)b * NPIX + pix) * 512;
            const size_t r1 = r0 + 8 * 512;
            #pragma unroll
            for (int ni = 0; ni < 4; ni++) {
                const int chl = warp_n * 32 + ni * 8 + l2;   // local 0..127
                const int chg = cg0 + chl;                   // global 0..255
                const float b0 = sbias[chl], b1 = sbias[chl + 1];
                #pragma unroll
                for (int h = 0; h < 2; h++) {
                    const size_t row = h ? r1 : r0;
                    float v0 = acc[mi][ni][h * 2 + 0] + b0;
                    float v1 = acc[mi][ni][h * 2 + 1] + b1;
                    float s0, c0, s1, c1;
                    __sincosf(v0, &s0, &c0);
                    __sincosf(v1, &s1, &c1);
                    __nv_bfloat16 sh0 = __float2bfloat16(s0), sh1 = __float2bfloat16(s1);
                    __nv_bfloat16 ch0 = __float2bfloat16(c0), ch1 = __float2bfloat16(c1);
                    uint32_t shi = (uint32_t)__bfloat16_as_ushort(sh0) |
                                   ((uint32_t)__bfloat16_as_ushort(sh1) << 16);
                    uint32_t chi = (uint32_t)__bfloat16_as_ushort(ch0) |
                                   ((uint32_t)__bfloat16_as_ushort(ch1) << 16);
                    uint32_t slo = packbf2(s0 - __bfloat162float(sh0), s1 - __bfloat162float(sh1));
                    uint32_t clo = packbf2(c0 - __bfloat162float(ch0), c1 - __bfloat162float(ch1));
                    *(uint32_t*)(Hh + row + chg)       = shi;
                    *(uint32_t*)(Hh + row + chg + 256) = chi;
                    *(uint32_t*)(Hl + row + chg)       = slo;
                    *(uint32_t*)(Hl + row + chg + 256) = clo;
                }
            }
        }
    } else {
        // stage smem [128 px][132] fp32 then coalesced channel-major writes
        float* smf = (float*)dsm;
        __syncthreads();
        #pragma unroll
        for (int mi = 0; mi < 4; mi++) {
            const int pxl0 = warp_m * 64 + mi * 16 + lg;
            #pragma unroll
            for (int ni = 0; ni < 4; ni++) {
                const int chl = warp_n * 32 + ni * 8 + l2;
                const float b0 = sbias[chl], b1 = sbias[chl + 1];
                smf[pxl0 * 132 + chl]           = acc[mi][ni][0] + b0;
                smf[pxl0 * 132 + chl + 1]       = acc[mi][ni][1] + b1;
                smf[(pxl0 + 8) * 132 + chl]     = acc[mi][ni][2] + b0;
                smf[(pxl0 + 8) * 132 + chl + 1] = acc[mi][ni][3] + b1;
            }
        }
        __syncthreads();
        const int ch = tid >> 1;           // 0..127
        const int pxh = (tid & 1) * 64;
        float* orow = out + ((size_t)b * 256 + cg0 + ch) * NPIX + p0 + pxh;
        #pragma unroll
        for (int g = 0; g < 16; g++) {
            float4 v;
            v.x = smf[(pxh + g * 4 + 0) * 132 + ch];
            v.y = smf[(pxh + g * 4 + 1) * 132 + ch];
            v.z = smf[(pxh + g * 4 + 2) * 132 + ch];
            v.w = smf[(pxh + g * 4 + 3) * 132 + ch];
            *(float4*)(orow + g * 4) = v;
        }
    }
}

// -------------------- launch ------------------------------------------------
extern "C" void kernel_launch(void* const* d_in, const int* in_sizes, int n_in,
                              void* d_out, int out_size) {
    const float* x           = (const float*)d_in[0];
    const float* lat         = (const float*)d_in[1];
    const float* k_in_mix    = (const float*)d_in[2];
    const float* k_mid_mix   = (const float*)d_in[3];
    const float* k_out_mix   = (const float*)d_in[4];
    const float* k_short_mix = (const float*)d_in[5];
    const float* b_in_mix    = (const float*)d_in[6];
    const float* b_mid_mix   = (const float*)d_in[7];
    const float* b_out_mix   = (const float*)d_in[8];
    const float* b_short_mix = (const float*)d_in[9];
    const float* w_dyna      = (const float*)d_in[10];
    const float* b_dyna      = (const float*)d_in[11];
    float* out = (float*)d_out;

    cudaFuncSetAttribute(gemm_stage<1>, cudaFuncAttributeMaxDynamicSharedMemorySize, SMEM_DYN);
    cudaFuncSetAttribute(gemm_stage<2>, cudaFuncAttributeMaxDynamicSharedMemorySize, SMEM_DYN);
    cudaFuncSetAttribute(gemm_stage<3>, cudaFuncAttributeMaxDynamicSharedMemorySize, SMEM_DYN);

    mix_kernel<<<1, 128>>>(lat, w_dyna, b_dyna);
    prep_kernel<<<1537, 256>>>(k_in_mix, k_mid_mix, k_out_mix, k_short_mix,
                               b_in_mix, b_mid_mix, b_out_mix, b_short_mix);
    xt_kernel<<<dim3(128, 8, 16), dim3(32, 8)>>>(x);
    gemm_stage<1><<<dim3(32, 2, 16), 256, SMEM_DYN>>>(out);
    gemm_stage<2><<<dim3(32, 2, 16), 256, SMEM_DYN>>>(out);
    gemm_stage<3><<<dim3(32, 2, 16), 256, SMEM_DYN>>>(out);
}

// round 4
// speedup vs baseline: 1.7204x; 1.0008x over previous
#include <cuda_runtime.h>
#include <cuda_bf16.h>
#include <cstdint>

// ============================================================================
// MixResidualBlockC via warp-level bf16 mma.sync (3-split fp32 emulation).
//   stage1: h1 = sincos(W1[256,256] @ xt)           (pixel-major bf16 hi/lo)
//   stage2: h2 = sincos(W2[256,512] @ h1)
//   stage3: out = W3[256,768] @ [h2 ; xt] + b3      (W3 = [k_out | k_short])
// CTA tile: 128 px x 128 ch.  Warp tile 64x32.  BK=64, smem rows padded 144B.
// R4: split-phase MMA sweeps -> acc RAW distance 16 (was 3, volatile-pinned).
// ============================================================================

#define NPIX 4096
#define NB 16
#define STRIDE 144                     // bytes per 64-bf16 smem row (padded)
#define PLANE (128 * STRIDE)           // 18432 B per plane tile
#define BUFSZ (4 * PLANE)              // Ah|Al|Bh|Bl = 73728 B
#define SMEM_DYN (2 * BUFSZ)           // 147456 B

// -------------------- device scratch --------------------------------------
__device__ float g_mix[NB * 8];
__device__ float g_b1[NB * 256], g_b2[NB * 256], g_b3[NB * 256];
__device__ __nv_bfloat16 g_w1h[NB * 256 * 256], g_w1l[NB * 256 * 256];
__device__ __nv_bfloat16 g_w2h[NB * 256 * 512], g_w2l[NB * 256 * 512];
__device__ __nv_bfloat16 g_w3h[NB * 256 * 768], g_w3l[NB * 256 * 768];
__device__ __nv_bfloat16 g_xth[(size_t)NB * NPIX * 256], g_xtl[(size_t)NB * NPIX * 256];
__device__ __nv_bfloat16 g_h1h[(size_t)NB * NPIX * 512], g_h1l[(size_t)NB * NPIX * 512];
__device__ __nv_bfloat16 g_h2h[(size_t)NB * NPIX * 512], g_h2l[(size_t)NB * NPIX * 512];

// -------------------- PTX helpers (all arch-portable) ----------------------
__device__ __forceinline__ uint32_t smem_u32(const void* p) {
    uint32_t a;
    asm("{ .reg .u64 t; cvta.to.shared.u64 t, %1; cvt.u32.u64 %0, t; }" : "=r"(a) : "l"(p));
    return a;
}
__device__ __forceinline__ void cpa16(uint32_t dst, const void* src) {
    asm volatile("cp.async.cg.shared.global [%0], [%1], 16;" :: "r"(dst), "l"(src));
}
__device__ __forceinline__ void cpa_commit() { asm volatile("cp.async.commit_group;"); }

__device__ __forceinline__ void ldsm_x4(uint32_t* r, uint32_t addr) {
    asm volatile("ldmatrix.sync.aligned.m8n8.x4.shared.b16 {%0,%1,%2,%3}, [%4];"
                 : "=r"(r[0]), "=r"(r[1]), "=r"(r[2]), "=r"(r[3]) : "r"(addr));
}
__device__ __forceinline__ void ldsm_x2(uint32_t* r, uint32_t addr) {
    asm volatile("ldmatrix.sync.aligned.m8n8.x2.shared.b16 {%0,%1}, [%2];"
                 : "=r"(r[0]), "=r"(r[1]) : "r"(addr));
}
__device__ __forceinline__ void mma_bf16(float* d, const uint32_t* a, const uint32_t* b) {
    asm volatile(
        "mma.sync.aligned.m16n8k16.row.col.f32.bf16.bf16.f32 "
        "{%0,%1,%2,%3}, {%4,%5,%6,%7}, {%8,%9}, {%0,%1,%2,%3};"
        : "+f"(d[0]), "+f"(d[1]), "+f"(d[2]), "+f"(d[3])
        : "r"(a[0]), "r"(a[1]), "r"(a[2]), "r"(a[3]), "r"(b[0]), "r"(b[1]));
}
__device__ __forceinline__ uint32_t packbf2(float a, float b) {
    __nv_bfloat16 h0 = __float2bfloat16(a), h1 = __float2bfloat16(b);
    return (uint32_t)__bfloat16_as_ushort(h0) | ((uint32_t)__bfloat16_as_ushort(h1) << 16);
}

// -------------------- K0: mixing coefficients ------------------------------
__global__ void mix_kernel(const float* __restrict__ lat, const float* __restrict__ wd,
                           const float* __restrict__ bd) {
    int t = threadIdx.x;
    if (t < 128) {
        int b = t >> 3, m = t & 7;
        float a = bd[m];
        const float* lp = lat + b * 512;
        const float* wp = wd + m * 512;
        #pragma unroll 8
        for (int l = 0; l < 512; l++) a += lp[l] * wp[l];
        g_mix[t] = a;
    }
}

// -------------------- K1: weight mixing + bf16 hi/lo split -----------------
__global__ void prep_kernel(const float* __restrict__ kin, const float* __restrict__ kmid,
                            const float* __restrict__ kout, const float* __restrict__ ksh,
                            const float* __restrict__ bin, const float* __restrict__ bmid,
                            const float* __restrict__ bout, const float* __restrict__ bsh) {
    __shared__ float smix[128];
    if (threadIdx.x < 128) smix[threadIdx.x] = g_mix[threadIdx.x];
    __syncthreads();
    int p = blockIdx.x * 256 + threadIdx.x;
    float v[8];

    if (p < 65536) {  // w1 (k_in)
        #pragma unroll
        for (int m = 0; m < 8; m++) v[m] = kin[m * 65536 + p];
        #pragma unroll
        for (int b = 0; b < NB; b++) {
            float a = 0.f;
            #pragma unroll
            for (int m = 0; m < 8; m++) a += smix[b * 8 + m] * v[m];
            __nv_bfloat16 h = __float2bfloat16(a);
            g_w1h[b * 65536 + p] = h;
            g_w1l[b * 65536 + p] = __float2bfloat16(a - __bfloat162float(h));
        }
    } else if (p < 196608) {  // w2 (k_mid)
        int q = p - 65536;
        #pragma unroll
        for (int m = 0; m < 8; m++) v[m] = kmid[m * 131072 + q];
        #pragma unroll
        for (int b = 0; b < NB; b++) {
            float a = 0.f;
            #pragma unroll
            for (int m = 0; m < 8; m++) a += smix[b * 8 + m] * v[m];
            __nv_bfloat16 h = __float2bfloat16(a);
            g_w2h[b * 131072 + q] = h;
            g_w2l[b * 131072 + q] = __float2bfloat16(a - __bfloat162float(h));
        }
    } else if (p < 327680) {  // w3 k_out part: cols [0,512)
        int q = p - 196608;
        int o = q >> 9, i = q & 511;
        #pragma unroll
        for (int m = 0; m < 8; m++) v[m] = kout[m * 131072 + q];
        int di = o * 768 + i;
        #pragma unroll
        for (int b = 0; b < NB; b++) {
            float a = 0.f;
            #pragma unroll
            for (int m = 0; m < 8; m++) a += smix[b * 8 + m] * v[m];
            __nv_bfloat16 h = __float2bfloat16(a);
            g_w3h[b * 196608 + di] = h;
            g_w3l[b * 196608 + di] = __float2bfloat16(a - __bfloat162float(h));
        }
    } else if (p < 393216) {  // w3 k_short part: cols [512,768)
        int q = p - 327680;
        int o = q >> 8, i = q & 255;
        #pragma unroll
        for (int m = 0; m < 8; m++) v[m] = ksh[m * 65536 + q];
        int di = o * 768 + 512 + i;
        #pragma unroll
        for (int b = 0; b < NB; b++) {
            float a = 0.f;
            #pragma unroll
            for (int m = 0; m < 8; m++) a += smix[b * 8 + m] * v[m];
            __nv_bfloat16 h = __float2bfloat16(a);
            g_w3h[b * 196608 + di] = h;
            g_w3l[b * 196608 + di] = __float2bfloat16(a - __bfloat162float(h));
        }
    } else if (p < 393472) {  // biases
        int r = p - 393216;
        float vi[8], vm[8], vo[8];
        #pragma unroll
        for (int m = 0; m < 8; m++) {
            vi[m] = bin[m * 256 + r];
            vm[m] = bmid[m * 256 + r];
            vo[m] = bout[m * 256 + r] + bsh[m * 256 + r];
        }
        #pragma unroll
        for (int b = 0; b < NB; b++) {
            float a1 = 0.f, a2 = 0.f, a3 = 0.f;
            #pragma unroll
            for (int m = 0; m < 8; m++) {
                float mx = smix[b * 8 + m];
                a1 += mx * vi[m]; a2 += mx * vm[m]; a3 += mx * vo[m];
            }
            g_b1[b * 256 + r] = a1;
            g_b2[b * 256 + r] = a2;
            g_b3[b * 256 + r] = a3;
        }
    }
}

// -------------------- K2: x transpose + split  x[b,c,p] -> xt[b,p,c] -------
__global__ void xt_kernel(const float* __restrict__ x) {
    __shared__ float ts[32][33];
    int b = blockIdx.z, p0 = blockIdx.x * 32, c0 = blockIdx.y * 32;
    const float* src = x + ((size_t)b * 256 + c0) * NPIX + p0;
    for (int r = threadIdx.y; r < 32; r += 8)
        ts[r][threadIdx.x] = src[(size_t)r * NPIX + threadIdx.x];
    __syncthreads();
    int lane = threadIdx.x;
    for (int pr = threadIdx.y; pr < 32; pr += 8) {
        float v = ts[lane][pr];
        __nv_bfloat16 h = __float2bfloat16(v);
        __nv_bfloat16 l = __float2bfloat16(v - __bfloat162float(h));
        size_t di = ((size_t)b * NPIX + p0 + pr) * 256 + c0 + lane;
        g_xth[di] = h;
        g_xtl[di] = l;
    }
}

// -------------------- GEMM stage (mma.sync bf16 3-split) -------------------
template <int MODE>  // 1,2,3
__global__ void __launch_bounds__(256, 1)
gemm_stage(float* __restrict__ out) {
    constexpr int K = (MODE == 1) ? 256 : (MODE == 2) ? 512 : 768;
    constexpr int NCH = K / 64;
    constexpr int AROW = (MODE == 1) ? 256 : 512;

    extern __shared__ __align__(16) char dsm[];
    const uint32_t sbase = smem_u32(dsm);
    __shared__ float sbias[128];

    const int tid = threadIdx.x;
    const int lane = tid & 31;
    const int wid = tid >> 5;
    const int warp_m = wid & 1;       // 0..1  (64 px each)
    const int warp_n = wid >> 1;      // 0..3  (32 ch each)
    const int b = blockIdx.z;
    const int p0 = blockIdx.x * 128;
    const int cg0 = blockIdx.y * 128;

    const __nv_bfloat16 *Ah, *Al, *Bh, *Bl;
    const float* bias;
    if constexpr (MODE == 1) {
        Ah = g_xth + (size_t)b * NPIX * 256; Al = g_xtl + (size_t)b * NPIX * 256;
        Bh = g_w1h + (size_t)b * 65536;      Bl = g_w1l + (size_t)b * 65536;
        bias = g_b1 + b * 256;
    } else if constexpr (MODE == 2) {
        Ah = g_h1h + (size_t)b * NPIX * 512; Al = g_h1l + (size_t)b * NPIX * 512;
        Bh = g_w2h + (size_t)b * 131072;     Bl = g_w2l + (size_t)b * 131072;
        bias = g_b2 + b * 256;
    } else {
        Ah = g_h2h + (size_t)b * NPIX * 512; Al = g_h2l + (size_t)b * NPIX * 512;
        Bh = g_w3h + (size_t)b * 196608;     Bl = g_w3l + (size_t)b * 196608;
        bias = g_b3 + b * 256;
    }
    const __nv_bfloat16* Xh = g_xth + (size_t)b * NPIX * 256;  // MODE3 tail
    const __nv_bfloat16* Xl = g_xtl + (size_t)b * NPIX * 256;

    if (tid < 128) sbias[tid] = bias[cg0 + tid];

    // ---- chunk copier: 4096 x 16B per chunk (Ah|Al|Bh|Bl, 128 rows x 8) ----
    auto copy_chunk = [&](int ch, int buf) {
        const int k0 = ch * 64;
        const uint32_t bb = sbase + buf * BUFSZ;
        const __nv_bfloat16 *pAh = Ah, *pAl = Al;
        int acol = k0, arow = AROW;
        if (MODE == 3 && k0 >= 512) { pAh = Xh; pAl = Xl; acol = k0 - 512; arow = 256; }
        #pragma unroll
        for (int j = 0; j < 16; j++) {
            int u = tid + j * 256;
            int plane = u >> 10;          // 0 Ah, 1 Al, 2 Bh, 3 Bl
            int r = (u >> 3) & 127;
            int c = u & 7;
            uint32_t dst = bb + plane * PLANE + r * STRIDE + c * 16;
            const __nv_bfloat16* src;
            if (plane == 0)      src = pAh + (size_t)(p0 + r) * arow + acol + c * 8;
            else if (plane == 1) src = pAl + (size_t)(p0 + r) * arow + acol + c * 8;
            else if (plane == 2) src = Bh + (size_t)(cg0 + r) * K + k0 + c * 8;
            else                 src = Bl + (size_t)(cg0 + r) * K + k0 + c * 8;
            cpa16(dst, src);
        }
        cpa_commit();
    };

    // ---- ldmatrix lane address offsets ----
    const int a_row_off = (warp_m * 64 + (lane & 15)) * STRIDE + ((lane >> 4) & 1) * 16;
    const int lb = lane & 15;
    const int b_row_off = (warp_n * 32 + (lb & 7)) * STRIDE + ((lb >> 3) & 1) * 16;

    float acc[4][4][4];
    #pragma unroll
    for (int i = 0; i < 4; i++)
        #pragma unroll
        for (int j = 0; j < 4; j++)
            #pragma unroll
            for (int q = 0; q < 4; q++) acc[i][j][q] = 0.f;

    copy_chunk(0, 0);
    asm volatile("cp.async.wait_group 0;" ::: "memory");
    __syncthreads();

    for (int it = 0; it < NCH; it++) {
        const int buf = it & 1;
        if (it + 1 < NCH) copy_chunk(it + 1, buf ^ 1);
        const uint32_t bb = sbase + buf * BUFSZ;

        #pragma unroll
        for (int ks = 0; ks < 4; ks++) {
            // ---- phase 1: Ah x Bh (16 independent MMAs; acc RAW dist = 16) ----
            uint32_t fAh[4][4], fBh[4][2];
            #pragma unroll
            for (int mi = 0; mi < 4; mi++)
                ldsm_x4(fAh[mi], bb + a_row_off + mi * (16 * STRIDE) + ks * 32);
            #pragma unroll
            for (int ni = 0; ni < 4; ni++)
                ldsm_x2(fBh[ni], bb + 2 * PLANE + b_row_off + ni * (8 * STRIDE) + ks * 32);
            #pragma unroll
            for (int mi = 0; mi < 4; mi++)
                #pragma unroll
                for (int ni = 0; ni < 4; ni++)
                    mma_bf16(acc[mi][ni], fAh[mi], fBh[ni]);

            // ---- phase 2: Ah x Bl ----
            uint32_t fBl[4][2];
            #pragma unroll
            for (int ni = 0; ni < 4; ni++)
                ldsm_x2(fBl[ni], bb + 3 * PLANE + b_row_off + ni * (8 * STRIDE) + ks * 32);
            #pragma unroll
            for (int mi = 0; mi < 4; mi++)
                #pragma unroll
                for (int ni = 0; ni < 4; ni++)
                    mma_bf16(acc[mi][ni], fAh[mi], fBl[ni]);

            // ---- phase 3: Al x Bh ----
            uint32_t fAl[4][4];
            #pragma unroll
            for (int mi = 0; mi < 4; mi++)
                ldsm_x4(fAl[mi], bb + PLANE + a_row_off + mi * (16 * STRIDE) + ks * 32);
            #pragma unroll
            for (int mi = 0; mi < 4; mi++)
                #pragma unroll
                for (int ni = 0; ni < 4; ni++)
                    mma_bf16(acc[mi][ni], fAl[mi], fBh[ni]);
        }
        if (it + 1 < NCH) {
            asm volatile("cp.async.wait_group 0;" ::: "memory");
            __syncthreads();
        }
    }

    // ---- epilogue -----------------------------------------------------------
    const int lg = lane >> 2;          // row-in-group 0..7
    const int l2 = (lane & 3) * 2;     // col pair

    if constexpr (MODE != 3) {
        __nv_bfloat16* Hh = (MODE == 1) ? g_h1h : g_h2h;
        __nv_bfloat16* Hl = (MODE == 1) ? g_h1l : g_h2l;
        #pragma unroll
        for (int mi = 0; mi < 4; mi++) {
            const int pix = p0 + warp_m * 64 + mi * 16 + lg;
            const size_t r0 = ((size_t)b * NPIX + pix) * 512;
            const size_t r1 = r0 + 8 * 512;
            #pragma unroll
            for (int ni = 0; ni < 4; ni++) {
                const int chl = warp_n * 32 + ni * 8 + l2;   // local 0..127
                const int chg = cg0 + chl;                   // global 0..255
                const float b0 = sbias[chl], b1 = sbias[chl + 1];
                #pragma unroll
                for (int h = 0; h < 2; h++) {
                    const size_t row = h ? r1 : r0;
                    float v0 = acc[mi][ni][h * 2 + 0] + b0;
                    float v1 = acc[mi][ni][h * 2 + 1] + b1;
                    float s0, c0, s1, c1;
                    __sincosf(v0, &s0, &c0);
                    __sincosf(v1, &s1, &c1);
                    __nv_bfloat16 sh0 = __float2bfloat16(s0), sh1 = __float2bfloat16(s1);
                    __nv_bfloat16 ch0 = __float2bfloat16(c0), ch1 = __float2bfloat16(c1);
                    uint32_t shi = (uint32_t)__bfloat16_as_ushort(sh0) |
                                   ((uint32_t)__bfloat16_as_ushort(sh1) << 16);
                    uint32_t chi = (uint32_t)__bfloat16_as_ushort(ch0) |
                                   ((uint32_t)__bfloat16_as_ushort(ch1) << 16);
                    uint32_t slo = packbf2(s0 - __bfloat162float(sh0), s1 - __bfloat162float(sh1));
                    uint32_t clo = packbf2(c0 - __bfloat162float(ch0), c1 - __bfloat162float(ch1));
                    *(uint32_t*)(Hh + row + chg)       = shi;
                    *(uint32_t*)(Hh + row + chg + 256) = chi;
                    *(uint32_t*)(Hl + row + chg)       = slo;
                    *(uint32_t*)(Hl + row + chg + 256) = clo;
                }
            }
        }
    } else {
        // stage smem [128 px][132] fp32 then coalesced channel-major writes
        float* smf = (float*)dsm;
        __syncthreads();
        #pragma unroll
        for (int mi = 0; mi < 4; mi++) {
            const int pxl0 = warp_m * 64 + mi * 16 + lg;
            #pragma unroll
            for (int ni = 0; ni < 4; ni++) {
                const int chl = warp_n * 32 + ni * 8 + l2;
                const float b0 = sbias[chl], b1 = sbias[chl + 1];
                smf[pxl0 * 132 + chl]           = acc[mi][ni][0] + b0;
                smf[pxl0 * 132 + chl + 1]       = acc[mi][ni][1] + b1;
                smf[(pxl0 + 8) * 132 + chl]     = acc[mi][ni][2] + b0;
                smf[(pxl0 + 8) * 132 + chl + 1] = acc[mi][ni][3] + b1;
            }
        }
        __syncthreads();
        const int ch = tid >> 1;           // 0..127
        const int pxh = (tid & 1) * 64;
        float* orow = out + ((size_t)b * 256 + cg0 + ch) * NPIX + p0 + pxh;
        #pragma unroll
        for (int g = 0; g < 16; g++) {
            float4 v;
            v.x = smf[(pxh + g * 4 + 0) * 132 + ch];
            v.y = smf[(pxh + g * 4 + 1) * 132 + ch];
            v.z = smf[(pxh + g * 4 + 2) * 132 + ch];
            v.w = smf[(pxh + g * 4 + 3) * 132 + ch];
            *(float4*)(orow + g * 4) = v;
        }
    }
}

// -------------------- launch ------------------------------------------------
extern "C" void kernel_launch(void* const* d_in, const int* in_sizes, int n_in,
                              void* d_out, int out_size) {
    const float* x           = (const float*)d_in[0];
    const float* lat         = (const float*)d_in[1];
    const float* k_in_mix    = (const float*)d_in[2];
    const float* k_mid_mix   = (const float*)d_in[3];
    const float* k_out_mix   = (const float*)d_in[4];
    const float* k_short_mix = (const float*)d_in[5];
    const float* b_in_mix    = (const float*)d_in[6];
    const float* b_mid_mix   = (const float*)d_in[7];
    const float* b_out_mix   = (const float*)d_in[8];
    const float* b_short_mix = (const float*)d_in[9];
    const float* w_dyna      = (const float*)d_in[10];
    const float* b_dyna      = (const float*)d_in[11];
    float* out = (float*)d_out;

    cudaFuncSetAttribute(gemm_stage<1>, cudaFuncAttributeMaxDynamicSharedMemorySize, SMEM_DYN);
    cudaFuncSetAttribute(gemm_stage<2>, cudaFuncAttributeMaxDynamicSharedMemorySize, SMEM_DYN);
    cudaFuncSetAttribute(gemm_stage<3>, cudaFuncAttributeMaxDynamicSharedMemorySize, SMEM_DYN);

    mix_kernel<<<1, 128>>>(lat, w_dyna, b_dyna);
    prep_kernel<<<1537, 256>>>(k_in_mix, k_mid_mix, k_out_mix, k_short_mix,
                               b_in_mix, b_mid_mix, b_out_mix, b_short_mix);
    xt_kernel<<<dim3(128, 8, 16), dim3(32, 8)>>>(x);
    gemm_stage<1><<<dim3(32, 2, 16), 256, SMEM_DYN>>>(out);
    gemm_stage<2><<<dim3(32, 2, 16), 256, SMEM_DYN>>>(out);
    gemm_stage<3><<<dim3(32, 2, 16), 256, SMEM_DYN>>>(out);
}